// round 1
// baseline (speedup 1.0000x reference)
#include <cuda_runtime.h>
#include <cuda_bf16.h>
#include <cstdint>
#include <cmath>

// ---------------- problem constants ----------------
#define Bc   4
#define Sc   2048
#define Dc   1024
#define Hh   16
#define DHh  64
#define FFc  4096
#define WINc 16
#define GMc  64
#define Rc   512
#define NWc  (Sc/WINc)     // 128
#define PAIRS (Sc/2)       // 1024
#define SKEEP (Sc-Rc)      // 1536
#define BS   (Bc*Sc)       // 8192

// ---------------- device scratch (static, no allocations) ----------------
__device__ float g_x2[(size_t)BS*Dc];    // residual stream (x2 -> x3 -> x4)
__device__ float g_h [(size_t)BS*Dc];    // normed activations
__device__ float g_q [(size_t)BS*Dc];
__device__ float g_k [(size_t)BS*Dc];
__device__ float g_v [(size_t)BS*Dc];
__device__ float g_o [(size_t)BS*Dc];
__device__ float g_f1[(size_t)BS*FFc];   // w1 branch / gated
__device__ float g_f3[(size_t)BS*FFc];   // w3 branch
__device__ float g_sim [Bc*PAIRS];
__device__ int   g_flag[Bc*PAIRS];
__device__ int   g_pf  [Bc*PAIRS];       // exclusive prefix of flags

// ---------------- fused (optional span-embed) + RMSNorm ----------------
template<bool ADDSPAN>
__global__ __launch_bounds__(256) void rmsnorm_k(
    const float* __restrict__ xin, const int* __restrict__ span,
    const float* __restrict__ w_span, const float* __restrict__ w_norm,
    float* __restrict__ x2, float* __restrict__ h)
{
    int row = blockIdx.x;                  // b*S + s
    __shared__ float buf[Dc];
    __shared__ float red[256];
    float lg = 0.f;
    if (ADDSPAN) lg = log1pf((float)span[row]);
    float ss = 0.f;
    const float* xr = xin + (size_t)row*Dc;
    for (int d = threadIdx.x; d < Dc; d += 256) {
        float v = xr[d];
        if (ADDSPAN) v += lg * w_span[d];
        buf[d] = v;
        ss += v*v;
    }
    red[threadIdx.x] = ss; __syncthreads();
    for (int s = 128; s > 0; s >>= 1) {
        if (threadIdx.x < s) red[threadIdx.x] += red[threadIdx.x+s];
        __syncthreads();
    }
    float scale = rsqrtf(red[0]/(float)Dc + 1e-6f);
    for (int d = threadIdx.x; d < Dc; d += 256) {
        float v = buf[d];
        if (ADDSPAN) x2[(size_t)row*Dc + d] = v;
        h[(size_t)row*Dc + d] = v * scale * w_norm[d];
    }
}

// ---------------- tiled fp32 SGEMM: C = [Rsd +] A(MxK) * W(KxN) ----------------
template<bool RES>
__global__ __launch_bounds__(256) void sgemm128(
    const float* __restrict__ A, const float* __restrict__ Wt,
    const float* __restrict__ Rsd, float* __restrict__ C,
    int M, int N, int K)
{
    const int BK = 8;
    __shared__ float As[BK][128];
    __shared__ float Bs[BK][128];
    int tid = threadIdx.x;
    int bn0 = blockIdx.x * 128;
    int bm0 = blockIdx.y * 128;
    int tx = tid & 15, ty = tid >> 4;
    int aRow = tid >> 1,  aCol = (tid & 1) * 4;
    int bRow = tid >> 5,  bCol = (tid & 31) * 4;
    float acc[8][8];
    #pragma unroll
    for (int m = 0; m < 8; m++)
        #pragma unroll
        for (int n = 0; n < 8; n++) acc[m][n] = 0.f;

    const float* Aptr = A + (size_t)(bm0 + aRow)*K + aCol;
    const float* Bptr = Wt + (size_t)bRow*N + bn0 + bCol;

    for (int k0 = 0; k0 < K; k0 += BK) {
        float4 av = *(const float4*)(Aptr + k0);
        As[aCol+0][aRow] = av.x; As[aCol+1][aRow] = av.y;
        As[aCol+2][aRow] = av.z; As[aCol+3][aRow] = av.w;
        float4 bv = *(const float4*)(Bptr + (size_t)k0*N);
        *(float4*)&Bs[bRow][bCol] = bv;
        __syncthreads();
        #pragma unroll
        for (int kk = 0; kk < BK; kk++) {
            float ra[8], rb[8];
            #pragma unroll
            for (int m = 0; m < 8; m++) ra[m] = As[kk][ty*8 + m];
            #pragma unroll
            for (int n = 0; n < 8; n++) rb[n] = Bs[kk][tx*8 + n];
            #pragma unroll
            for (int m = 0; m < 8; m++)
                #pragma unroll
                for (int n = 0; n < 8; n++)
                    acc[m][n] += ra[m]*rb[n];
        }
        __syncthreads();
    }
    #pragma unroll
    for (int m = 0; m < 8; m++) {
        int row = bm0 + ty*8 + m;
        float* cp = C + (size_t)row*N + bn0 + tx*8;
        const float* rp = RES ? (Rsd + (size_t)row*N + bn0 + tx*8) : nullptr;
        #pragma unroll
        for (int n = 0; n < 8; n += 4) {
            float4 o;
            o.x = acc[m][n+0]; o.y = acc[m][n+1]; o.z = acc[m][n+2]; o.w = acc[m][n+3];
            if (RES) { float4 rv = *(const float4*)(rp + n);
                       o.x += rv.x; o.y += rv.y; o.z += rv.z; o.w += rv.w; }
            *(float4*)(cp + n) = o;
        }
    }
}

// ---------------- RoPE on q and k ----------------
__global__ void rope_kernel(float* __restrict__ q, float* __restrict__ k,
                            const int* __restrict__ pos_ids,
                            const float* __restrict__ freqs)
{
    int idx = blockIdx.x * blockDim.x + threadIdx.x;   // B*S*H*32
    if (idx >= Bc*Sc*Hh*32) return;
    int f  = idx & 31;
    int h  = (idx >> 5) & (Hh-1);
    int s  = (idx >> 9) & (Sc-1);
    int b  = idx >> 20;
    float pos = (float)pos_ids[b*Sc + s];
    float ang = pos * freqs[f];
    float sn, cs;
    sincosf(ang, &sn, &cs);
    size_t base = ((size_t)(b*Sc + s))*Dc + h*DHh + f;
    float t1 = q[base], t2 = q[base+32];
    q[base]    = t1*cs - t2*sn;
    q[base+32] = t1*sn + t2*cs;
    t1 = k[base]; t2 = k[base+32];
    k[base]    = t1*cs - t2*sn;
    k[base+32] = t1*sn + t2*cs;
}

// ---------------- windowed attention: one block per (b, window, head) ----------------
__global__ __launch_bounds__(256) void attn_kernel(
    const float* __restrict__ q, const float* __restrict__ k,
    const float* __restrict__ v, float* __restrict__ o)
{
    int bid = blockIdx.x;
    int h = bid & (Hh-1);
    int n = (bid / Hh) & (NWc-1);
    int b = bid / (Hh*NWc);
    int s0 = n * WINc;

    __shared__ float qs[WINc][DHh+1];
    __shared__ float ks[WINc][DHh+1];
    __shared__ float vs[WINc][DHh+1];
    __shared__ float ps[WINc][WINc+1];

    int tid = threadIdx.x;
    // load 16x64 tiles (1024 elems each; 4 per thread)
    for (int t = 0; t < 4; t++) {
        int i = tid + t*256;
        int r = i >> 6, d = i & 63;
        size_t ga = ((size_t)(b*Sc + s0 + r))*Dc + h*DHh + d;
        qs[r][d] = q[ga];
        ks[r][d] = k[ga];
        vs[r][d] = v[ga];
    }
    __syncthreads();
    // scores
    {
        int i = tid >> 4, j = tid & 15;
        float acc = 0.f;
        #pragma unroll
        for (int d = 0; d < DHh; d++) acc += qs[i][d]*ks[j][d];
        ps[i][j] = acc * 0.125f;
    }
    __syncthreads();
    // softmax per row
    if (tid < WINc) {
        int i = tid;
        float mx = ps[i][0];
        #pragma unroll
        for (int j = 1; j < WINc; j++) mx = fmaxf(mx, ps[i][j]);
        float sum = 0.f;
        float e[WINc];
        #pragma unroll
        for (int j = 0; j < WINc; j++) { e[j] = expf(ps[i][j]-mx); sum += e[j]; }
        float inv = 1.f/sum;
        #pragma unroll
        for (int j = 0; j < WINc; j++) ps[i][j] = e[j]*inv;
    }
    __syncthreads();
    // output 16x64
    for (int t = 0; t < 4; t++) {
        int i = tid + t*256;
        int r = i >> 6, d = i & 63;
        float acc = 0.f;
        #pragma unroll
        for (int j = 0; j < WINc; j++) acc += ps[r][j]*vs[j][d];
        o[((size_t)(b*Sc + s0 + r))*Dc + h*DHh + d] = acc;
    }
}

// ---------------- SiLU(a) * b, in place into a ----------------
__global__ void silu_mul(float* __restrict__ a, const float* __restrict__ bb, int n4)
{
    int i = blockIdx.x*blockDim.x + threadIdx.x;
    if (i >= n4) return;
    float4 av = ((float4*)a)[i];
    float4 bv = ((const float4*)bb)[i];
    av.x = av.x/(1.f+expf(-av.x))*bv.x;
    av.y = av.y/(1.f+expf(-av.y))*bv.y;
    av.z = av.z/(1.f+expf(-av.z))*bv.z;
    av.w = av.w/(1.f+expf(-av.w))*bv.w;
    ((float4*)a)[i] = av;
}

// ---------------- metric + cosine sim per token pair ----------------
__global__ __launch_bounds__(256) void pair_sim(
    const float* __restrict__ x, const float* __restrict__ src,
    const float* __restrict__ pad, const float* __restrict__ w_metric,
    float* __restrict__ sim)
{
    int bp = blockIdx.x;
    int b = bp >> 10, j = bp & 1023;
    int re = 2*j;
    __shared__ float xe[Dc], xo[Dc];
    __shared__ float met[2*GMc];
    __shared__ float red[256];
    int tid = threadIdx.x;
    const float* xre = x + ((size_t)(b*Sc + re))*Dc;
    const float* xro = xre + Dc;
    for (int d = tid; d < Dc; d += 256) { xe[d] = xre[d]; xo[d] = xro[d]; }
    // real = (source * pad).sum(-1) > 0 for both rows
    float se = 0.f, so = 0.f;
    const float* s_e = src + ((size_t)(b*Sc + re))*Sc;
    const float* s_o = s_e + Sc;
    const float* pd  = pad + b*Sc;
    for (int d = tid; d < Sc; d += 256) { se += s_e[d]*pd[d]; so += s_o[d]*pd[d]; }
    __syncthreads();
    // metric dots (64 per row)
    if (tid < 2*GMc) {
        int r = tid >> 6, g = tid & 63;
        const float* xr = r ? xo : xe;
        float acc = 0.f;
        for (int d = 0; d < Dc; d++) acc += xr[d]*w_metric[d*GMc + g];
        met[tid] = acc;
    }
    __syncthreads();
    red[tid] = se; __syncthreads();
    for (int s = 128; s > 0; s >>= 1) { if (tid < s) red[tid] += red[tid+s]; __syncthreads(); }
    float real_e = red[0]; __syncthreads();
    red[tid] = so; __syncthreads();
    for (int s = 128; s > 0; s >>= 1) { if (tid < s) red[tid] += red[tid+s]; __syncthreads(); }
    float real_o = red[0]; __syncthreads();
    if (tid == 0) {
        float ne = 0.f, no = 0.f, dp = 0.f;
        #pragma unroll
        for (int g = 0; g < GMc; g++) {
            float a = met[g], bb2 = met[GMc+g];
            ne += a*a; no += bb2*bb2; dp += a*bb2;
        }
        ne = sqrtf(ne) + 1e-6f;
        no = sqrtf(no) + 1e-6f;
        float s2 = dp/(ne*no);
        bool ok = (real_e > 0.f) && (real_o > 0.f);
        sim[b*PAIRS + j] = ok ? s2 : -10000.0f;
    }
}

// ---------------- exact top-k flags (jax.lax.top_k semantics) + prefix ----------------
__global__ __launch_bounds__(1024) void topk_kernel(
    const float* __restrict__ sim, int* __restrict__ flag, int* __restrict__ pf)
{
    int b = blockIdx.x;
    __shared__ float ss[PAIRS];
    __shared__ int   fl[PAIRS];
    int t = threadIdx.x;
    ss[t] = sim[b*PAIRS + t];
    __syncthreads();
    float mine = ss[t];
    int rank = 0;
    for (int j = 0; j < PAIRS; j++) {
        float v = ss[j];
        rank += (v > mine) || (v == mine && j < t);
    }
    int f = (rank < Rc) ? 1 : 0;
    flag[b*PAIRS + t] = f;
    fl[t] = f;
    __syncthreads();
    if (t == 0) {
        int run = 0;
        for (int m = 0; m < PAIRS; m++) { pf[b*PAIRS + m] = run; run += fl[m]; }
    }
}

// ---------------- merge + gather + emit all four outputs ----------------
__global__ __launch_bounds__(256) void emit_kernel(
    const float* __restrict__ x, const float* __restrict__ src,
    const int* __restrict__ pos_ids, const int* __restrict__ span,
    const int* __restrict__ flag, const int* __restrict__ pf,
    float* __restrict__ out)
{
    int bid = blockIdx.x;
    int b = bid >> 11;           // /S
    int i = bid & (Sc-1);
    int m = i >> 1;
    int f = flag[b*PAIRS + m];
    bool odd = (i & 1) != 0;
    if (odd && f) return;        // dropped
    int t = i - pf[b*PAIRS + m];

    const size_t OX  = 0;
    const size_t OS  = (size_t)Bc*SKEEP*Dc;
    const size_t OP  = OS + (size_t)Bc*SKEEP*Sc;
    const size_t OSP = OP + (size_t)Bc*SKEEP;

    float* ox  = out + OX + ((size_t)b*SKEEP + t)*Dc;
    float* osr = out + OS + ((size_t)b*SKEEP + t)*Sc;
    const float* xi = x   + ((size_t)(b*Sc + i))*Dc;
    const float* si = src + ((size_t)(b*Sc + i))*Sc;

    bool merge = (!odd) && f;
    if (merge) {
        float sev = (float)span[b*Sc + i];
        float sov = (float)span[b*Sc + i + 1];
        float tot = sev + sov;
        const float* xn = xi + Dc;
        for (int d = threadIdx.x; d < Dc; d += 256)
            ox[d] = (sev*xi[d] + sov*xn[d]) / tot;
        const float* sn2 = si + Sc;
        for (int d = threadIdx.x; d < Sc; d += 256)
            osr[d] = si[d] + sn2[d];
    } else {
        for (int d = threadIdx.x; d < Dc; d += 256) ox[d] = xi[d];
        for (int d = threadIdx.x; d < Sc; d += 256) osr[d] = si[d];
    }
    if (threadIdx.x == 0) {
        out[OP  + (size_t)b*SKEEP + t] = (float)pos_ids[b*Sc + i];
        int sp = span[b*Sc + i];
        if (merge) sp += span[b*Sc + i + 1];
        out[OSP + (size_t)b*SKEEP + t] = (float)sp;
    }
}

// ---------------- host launcher ----------------
extern "C" void kernel_launch(void* const* d_in, const int* in_sizes, int n_in,
                              void* d_out, int out_size)
{
    // input order: x, source, position_ids, span_ids, [r], rope_freqs, pad_mask,
    //              seq_pad_mask, w_span, w_norm1, wq, wk, wv, wo, w_norm2, w1, w3, w2, w_metric
    int ro = (n_in >= 19) ? 0 : -1;   // r present as scalar input?
    const float* x        = (const float*)d_in[0];
    const float* source   = (const float*)d_in[1];
    const int*   pos_ids  = (const int*)  d_in[2];
    const int*   span     = (const int*)  d_in[3];
    const float* freqs    = (const float*)d_in[5+ro];
    const float* pad      = (const float*)d_in[6+ro];
    const float* w_span   = (const float*)d_in[8+ro];
    const float* w_norm1  = (const float*)d_in[9+ro];
    const float* wq       = (const float*)d_in[10+ro];
    const float* wk       = (const float*)d_in[11+ro];
    const float* wv       = (const float*)d_in[12+ro];
    const float* wo       = (const float*)d_in[13+ro];
    const float* w_norm2  = (const float*)d_in[14+ro];
    const float* w1       = (const float*)d_in[15+ro];
    const float* w3       = (const float*)d_in[16+ro];
    const float* w2       = (const float*)d_in[17+ro];
    const float* w_metric = (const float*)d_in[18+ro];
    float* out = (float*)d_out;

    float *px2, *ph, *pq, *pk, *pv, *po, *pf1, *pf3, *psim;
    int *pflag, *ppf;
    cudaGetSymbolAddress((void**)&px2,  g_x2);
    cudaGetSymbolAddress((void**)&ph,   g_h);
    cudaGetSymbolAddress((void**)&pq,   g_q);
    cudaGetSymbolAddress((void**)&pk,   g_k);
    cudaGetSymbolAddress((void**)&pv,   g_v);
    cudaGetSymbolAddress((void**)&po,   g_o);
    cudaGetSymbolAddress((void**)&pf1,  g_f1);
    cudaGetSymbolAddress((void**)&pf3,  g_f3);
    cudaGetSymbolAddress((void**)&psim, g_sim);
    cudaGetSymbolAddress((void**)&pflag,g_flag);
    cudaGetSymbolAddress((void**)&ppf,  g_pf);

    // 1) x2 = x + span-embed ; h = rmsnorm1(x2)
    rmsnorm_k<true><<<BS, 256>>>(x, span, w_span, w_norm1, px2, ph);
    // 2) q,k,v projections
    dim3 gD(Dc/128, BS/128);
    sgemm128<false><<<gD, 256>>>(ph, wq, nullptr, pq, BS, Dc, Dc);
    sgemm128<false><<<gD, 256>>>(ph, wk, nullptr, pk, BS, Dc, Dc);
    sgemm128<false><<<gD, 256>>>(ph, wv, nullptr, pv, BS, Dc, Dc);
    // 3) rope on q,k
    rope_kernel<<<(Bc*Sc*Hh*32)/256, 256>>>(pq, pk, pos_ids, freqs);
    // 4) windowed attention
    attn_kernel<<<Bc*NWc*Hh, 256>>>(pq, pk, pv, po);
    // 5) x3 = x2 + o @ wo  (in place into g_x2)
    sgemm128<true><<<gD, 256>>>(po, wo, px2, px2, BS, Dc, Dc);
    // 6) h = rmsnorm2(x3)
    rmsnorm_k<false><<<BS, 256>>>(px2, nullptr, nullptr, w_norm2, nullptr, ph);
    // 7) FFN branches
    dim3 gF(FFc/128, BS/128);
    sgemm128<false><<<gF, 256>>>(ph, w1, nullptr, pf1, BS, FFc, Dc);
    sgemm128<false><<<gF, 256>>>(ph, w3, nullptr, pf3, BS, FFc, Dc);
    silu_mul<<<((size_t)BS*FFc/4 + 255)/256, 256>>>(pf1, pf3, BS*FFc/4);
    // 8) x4 = x3 + gated @ w2  (in place)
    sgemm128<true><<<gD, 256>>>(pf1, w2, px2, px2, BS, Dc, FFc);
    // 9) metric + cosine sim per pair (with pair_ok from source*pad)
    pair_sim<<<Bc*PAIRS, 256>>>(px2, source, pad, w_metric, psim);
    // 10) exact top-k flags + prefix
    topk_kernel<<<Bc, 1024>>>(psim, pflag, ppf);
    // 11) merge + gather + emit (x_full, src_full, pos_full, sp_full) as f32
    emit_kernel<<<Bc*Sc, 256>>>(px2, source, pos_ids, span, pflag, ppf, out);
    (void)in_sizes; (void)out_size;
}

// round 2
// speedup vs baseline: 1.0587x; 1.0587x over previous
#include <cuda_runtime.h>
#include <cuda_bf16.h>
#include <cstdint>
#include <cmath>

// ---------------- problem constants ----------------
#define Bc   4
#define Sc   2048
#define Dc   1024
#define Hh   16
#define DHh  64
#define FFc  4096
#define WINc 16
#define GMc  64
#define Rc   512
#define NWc  (Sc/WINc)     // 128
#define PAIRS (Sc/2)       // 1024
#define SKEEP (Sc-Rc)      // 1536
#define BS   (Bc*Sc)       // 8192

// ---------------- device scratch (static, no allocations) ----------------
__device__ float g_x2[(size_t)BS*Dc];    // residual stream (x2 -> x3 -> x4)
__device__ float g_h [(size_t)BS*Dc];    // normed activations
__device__ float g_q [(size_t)BS*Dc];
__device__ float g_k [(size_t)BS*Dc];
__device__ float g_v [(size_t)BS*Dc];
__device__ float g_o [(size_t)BS*Dc];
__device__ float g_f1[(size_t)BS*FFc];   // w1 branch -> gated
__device__ float g_sim [Bc*PAIRS];
__device__ int   g_flag[Bc*PAIRS];
__device__ int   g_pf  [Bc*PAIRS];       // exclusive prefix of flags

// ---------------- fused (optional span-embed) + RMSNorm ----------------
template<bool ADDSPAN>
__global__ __launch_bounds__(256) void rmsnorm_k(
    const float* __restrict__ xin, const int* __restrict__ span,
    const float* __restrict__ w_span, const float* __restrict__ w_norm,
    float* __restrict__ x2, float* __restrict__ h)
{
    int row = blockIdx.x;                  // b*S + s
    __shared__ float buf[Dc];
    __shared__ float red[256];
    float lg = 0.f;
    if (ADDSPAN) lg = log1pf((float)span[row]);
    float ss = 0.f;
    const float* xr = xin + (size_t)row*Dc;
    for (int d = threadIdx.x; d < Dc; d += 256) {
        float v = xr[d];
        if (ADDSPAN) v += lg * w_span[d];
        buf[d] = v;
        ss += v*v;
    }
    red[threadIdx.x] = ss; __syncthreads();
    for (int s = 128; s > 0; s >>= 1) {
        if (threadIdx.x < s) red[threadIdx.x] += red[threadIdx.x+s];
        __syncthreads();
    }
    float scale = rsqrtf(red[0]/(float)Dc + 1e-6f);
    for (int d = threadIdx.x; d < Dc; d += 256) {
        float v = buf[d];
        if (ADDSPAN) x2[(size_t)row*Dc + d] = v;
        h[(size_t)row*Dc + d] = v * scale * w_norm[d];
    }
}

// ---------------- double-buffered fp32 SGEMM ----------------
// EPI: 0 -> C = A*B
//      1 -> C = AUX + A*B                 (residual)
//      2 -> C = silu(AUX) * (A*B)         (gated FFN, AUX==C allowed in-place)
template<int EPI>
__global__ __launch_bounds__(256) void sgemm_db(
    const float* __restrict__ A, const float* __restrict__ B,
    const float* __restrict__ AUX, float* __restrict__ C,
    int M, int N, int K)
{
    __shared__ float As[2][8][128];
    __shared__ float Bs[2][8][128];
    int tid = threadIdx.x;
    int bn0 = blockIdx.x * 128;
    int bm0 = blockIdx.y * 128;
    int tx = tid & 15, ty = tid >> 4;

    int aRow = tid >> 1,  aCol = (tid & 1) * 4;
    int bRow = tid >> 5,  bCol = (tid & 31) * 4;

    const float* Aptr = A + (size_t)(bm0 + aRow)*K + aCol;
    const float* Bptr = B + (size_t)bRow*N + bn0 + bCol;

    // preload tile 0
    float4 av = *(const float4*)(Aptr);
    float4 bv = *(const float4*)(Bptr);
    As[0][aCol+0][aRow] = av.x; As[0][aCol+1][aRow] = av.y;
    As[0][aCol+2][aRow] = av.z; As[0][aCol+3][aRow] = av.w;
    *(float4*)&Bs[0][bRow][bCol] = bv;
    __syncthreads();

    float acc[8][8];
    #pragma unroll
    for (int m = 0; m < 8; m++)
        #pragma unroll
        for (int n = 0; n < 8; n++) acc[m][n] = 0.f;

    int buf = 0;
    for (int k0 = 8; k0 <= K; k0 += 8) {
        bool more = (k0 < K);
        if (more) {
            av = *(const float4*)(Aptr + k0);
            bv = *(const float4*)(Bptr + (size_t)k0*N);
        }
        #pragma unroll
        for (int kk = 0; kk < 8; kk++) {
            float4 a0 = *(const float4*)&As[buf][kk][ty*8];
            float4 a1 = *(const float4*)&As[buf][kk][ty*8+4];
            float4 b0 = *(const float4*)&Bs[buf][kk][tx*8];
            float4 b1 = *(const float4*)&Bs[buf][kk][tx*8+4];
            float ra[8] = {a0.x,a0.y,a0.z,a0.w,a1.x,a1.y,a1.z,a1.w};
            float rb[8] = {b0.x,b0.y,b0.z,b0.w,b1.x,b1.y,b1.z,b1.w};
            #pragma unroll
            for (int m = 0; m < 8; m++)
                #pragma unroll
                for (int n = 0; n < 8; n++)
                    acc[m][n] += ra[m]*rb[n];
        }
        if (more) {
            buf ^= 1;
            As[buf][aCol+0][aRow] = av.x; As[buf][aCol+1][aRow] = av.y;
            As[buf][aCol+2][aRow] = av.z; As[buf][aCol+3][aRow] = av.w;
            *(float4*)&Bs[buf][bRow][bCol] = bv;
            __syncthreads();
        }
    }

    #pragma unroll
    for (int m = 0; m < 8; m++) {
        int row = bm0 + ty*8 + m;
        float* cp = C + (size_t)row*N + bn0 + tx*8;
        const float* rp = (EPI != 0) ? (AUX + (size_t)row*N + bn0 + tx*8) : nullptr;
        #pragma unroll
        for (int n = 0; n < 8; n += 4) {
            float4 o;
            o.x = acc[m][n+0]; o.y = acc[m][n+1]; o.z = acc[m][n+2]; o.w = acc[m][n+3];
            if (EPI == 1) {
                float4 rv = *(const float4*)(rp + n);
                o.x += rv.x; o.y += rv.y; o.z += rv.z; o.w += rv.w;
            } else if (EPI == 2) {
                float4 rv = *(const float4*)(rp + n);
                o.x *= rv.x/(1.f+expf(-rv.x));
                o.y *= rv.y/(1.f+expf(-rv.y));
                o.z *= rv.z/(1.f+expf(-rv.z));
                o.w *= rv.w/(1.f+expf(-rv.w));
            }
            *(float4*)(cp + n) = o;
        }
    }
}

// ---------------- RoPE on q and k ----------------
__global__ void rope_kernel(float* __restrict__ q, float* __restrict__ k,
                            const int* __restrict__ pos_ids,
                            const float* __restrict__ freqs)
{
    int idx = blockIdx.x * blockDim.x + threadIdx.x;   // B*S*H*32
    if (idx >= Bc*Sc*Hh*32) return;
    int f  = idx & 31;
    int h  = (idx >> 5) & (Hh-1);
    int s  = (idx >> 9) & (Sc-1);
    int b  = idx >> 20;
    float pos = (float)pos_ids[b*Sc + s];
    float ang = pos * freqs[f];
    float sn, cs;
    sincosf(ang, &sn, &cs);
    size_t base = ((size_t)(b*Sc + s))*Dc + h*DHh + f;
    float t1 = q[base], t2 = q[base+32];
    q[base]    = t1*cs - t2*sn;
    q[base+32] = t1*sn + t2*cs;
    t1 = k[base]; t2 = k[base+32];
    k[base]    = t1*cs - t2*sn;
    k[base+32] = t1*sn + t2*cs;
}

// ---------------- windowed attention: one block per (b, window, head) ----------------
__global__ __launch_bounds__(256) void attn_kernel(
    const float* __restrict__ q, const float* __restrict__ k,
    const float* __restrict__ v, float* __restrict__ o)
{
    int bid = blockIdx.x;
    int h = bid & (Hh-1);
    int n = (bid / Hh) & (NWc-1);
    int b = bid / (Hh*NWc);
    int s0 = n * WINc;

    __shared__ float qs[WINc][DHh+1];
    __shared__ float ks[WINc][DHh+1];
    __shared__ float vs[WINc][DHh+1];
    __shared__ float ps[WINc][WINc+1];

    int tid = threadIdx.x;
    for (int t = 0; t < 4; t++) {
        int i = tid + t*256;
        int r = i >> 6, d = i & 63;
        size_t ga = ((size_t)(b*Sc + s0 + r))*Dc + h*DHh + d;
        qs[r][d] = q[ga];
        ks[r][d] = k[ga];
        vs[r][d] = v[ga];
    }
    __syncthreads();
    {
        int i = tid >> 4, j = tid & 15;
        float acc = 0.f;
        #pragma unroll
        for (int d = 0; d < DHh; d++) acc += qs[i][d]*ks[j][d];
        ps[i][j] = acc * 0.125f;
    }
    __syncthreads();
    if (tid < WINc) {
        int i = tid;
        float mx = ps[i][0];
        #pragma unroll
        for (int j = 1; j < WINc; j++) mx = fmaxf(mx, ps[i][j]);
        float sum = 0.f;
        float e[WINc];
        #pragma unroll
        for (int j = 0; j < WINc; j++) { e[j] = expf(ps[i][j]-mx); sum += e[j]; }
        float inv = 1.f/sum;
        #pragma unroll
        for (int j = 0; j < WINc; j++) ps[i][j] = e[j]*inv;
    }
    __syncthreads();
    for (int t = 0; t < 4; t++) {
        int i = tid + t*256;
        int r = i >> 6, d = i & 63;
        float acc = 0.f;
        #pragma unroll
        for (int j = 0; j < WINc; j++) acc += ps[r][j]*vs[j][d];
        o[((size_t)(b*Sc + s0 + r))*Dc + h*DHh + d] = acc;
    }
}

// ---------------- metric + cosine sim per token pair ----------------
__global__ __launch_bounds__(256) void pair_sim(
    const float* __restrict__ x, const float* __restrict__ src,
    const float* __restrict__ pad, const float* __restrict__ w_metric,
    float* __restrict__ sim)
{
    int bp = blockIdx.x;
    int b = bp >> 10, j = bp & 1023;
    int re = 2*j;
    __shared__ float xe[Dc], xo[Dc];
    __shared__ float met[2*GMc];
    __shared__ float red[256];
    int tid = threadIdx.x;
    const float* xre = x + ((size_t)(b*Sc + re))*Dc;
    const float* xro = xre + Dc;
    for (int d = tid; d < Dc; d += 256) { xe[d] = xre[d]; xo[d] = xro[d]; }
    float se = 0.f, so = 0.f;
    const float* s_e = src + ((size_t)(b*Sc + re))*Sc;
    const float* s_o = s_e + Sc;
    const float* pd  = pad + b*Sc;
    for (int d = tid; d < Sc; d += 256) { se += s_e[d]*pd[d]; so += s_o[d]*pd[d]; }
    __syncthreads();
    if (tid < 2*GMc) {
        int r = tid >> 6, g = tid & 63;
        const float* xr = r ? xo : xe;
        float acc = 0.f;
        for (int d = 0; d < Dc; d++) acc += xr[d]*w_metric[d*GMc + g];
        met[tid] = acc;
    }
    __syncthreads();
    red[tid] = se; __syncthreads();
    for (int s = 128; s > 0; s >>= 1) { if (tid < s) red[tid] += red[tid+s]; __syncthreads(); }
    float real_e = red[0]; __syncthreads();
    red[tid] = so; __syncthreads();
    for (int s = 128; s > 0; s >>= 1) { if (tid < s) red[tid] += red[tid+s]; __syncthreads(); }
    float real_o = red[0]; __syncthreads();
    if (tid == 0) {
        float ne = 0.f, no = 0.f, dp = 0.f;
        #pragma unroll
        for (int g = 0; g < GMc; g++) {
            float a = met[g], bb2 = met[GMc+g];
            ne += a*a; no += bb2*bb2; dp += a*bb2;
        }
        ne = sqrtf(ne) + 1e-6f;
        no = sqrtf(no) + 1e-6f;
        float s2 = dp/(ne*no);
        bool ok = (real_e > 0.f) && (real_o > 0.f);
        sim[b*PAIRS + j] = ok ? s2 : -10000.0f;
    }
}

// ---------------- exact top-k flags (jax.lax.top_k semantics) + prefix ----------------
__global__ __launch_bounds__(1024) void topk_kernel(
    const float* __restrict__ sim, int* __restrict__ flag, int* __restrict__ pf)
{
    int b = blockIdx.x;
    __shared__ float ss[PAIRS];
    __shared__ int   fl[PAIRS];
    int t = threadIdx.x;
    ss[t] = sim[b*PAIRS + t];
    __syncthreads();
    float mine = ss[t];
    int rank = 0;
    for (int j = 0; j < PAIRS; j++) {
        float v = ss[j];
        rank += (v > mine) || (v == mine && j < t);
    }
    int f = (rank < Rc) ? 1 : 0;
    flag[b*PAIRS + t] = f;
    fl[t] = f;
    __syncthreads();
    if (t == 0) {
        int run = 0;
        for (int m = 0; m < PAIRS; m++) { pf[b*PAIRS + m] = run; run += fl[m]; }
    }
}

// ---------------- merge + gather + emit all four outputs ----------------
__global__ __launch_bounds__(256) void emit_kernel(
    const float* __restrict__ x, const float* __restrict__ src,
    const int* __restrict__ pos_ids, const int* __restrict__ span,
    const int* __restrict__ flag, const int* __restrict__ pf,
    float* __restrict__ out)
{
    int bid = blockIdx.x;
    int b = bid >> 11;           // /S
    int i = bid & (Sc-1);
    int m = i >> 1;
    int f = flag[b*PAIRS + m];
    bool odd = (i & 1) != 0;
    if (odd && f) return;        // dropped
    int t = i - pf[b*PAIRS + m];

    const size_t OX  = 0;
    const size_t OS  = (size_t)Bc*SKEEP*Dc;
    const size_t OP  = OS + (size_t)Bc*SKEEP*Sc;
    const size_t OSP = OP + (size_t)Bc*SKEEP;

    float* ox  = out + OX + ((size_t)b*SKEEP + t)*Dc;
    float* osr = out + OS + ((size_t)b*SKEEP + t)*Sc;
    const float* xi = x   + ((size_t)(b*Sc + i))*Dc;
    const float* si = src + ((size_t)(b*Sc + i))*Sc;

    bool merge = (!odd) && f;
    if (merge) {
        float sev = (float)span[b*Sc + i];
        float sov = (float)span[b*Sc + i + 1];
        float tot = sev + sov;
        const float* xn = xi + Dc;
        for (int d = threadIdx.x; d < Dc; d += 256)
            ox[d] = (sev*xi[d] + sov*xn[d]) / tot;
        const float* sn2 = si + Sc;
        for (int d = threadIdx.x; d < Sc; d += 256)
            osr[d] = si[d] + sn2[d];
    } else {
        for (int d = threadIdx.x; d < Dc; d += 256) ox[d] = xi[d];
        for (int d = threadIdx.x; d < Sc; d += 256) osr[d] = si[d];
    }
    if (threadIdx.x == 0) {
        out[OP  + (size_t)b*SKEEP + t] = (float)pos_ids[b*Sc + i];
        int sp = span[b*Sc + i];
        if (merge) sp += span[b*Sc + i + 1];
        out[OSP + (size_t)b*SKEEP + t] = (float)sp;
    }
}

// ---------------- host launcher ----------------
extern "C" void kernel_launch(void* const* d_in, const int* in_sizes, int n_in,
                              void* d_out, int out_size)
{
    int ro = (n_in >= 19) ? 0 : -1;   // r present as scalar input?
    const float* x        = (const float*)d_in[0];
    const float* source   = (const float*)d_in[1];
    const int*   pos_ids  = (const int*)  d_in[2];
    const int*   span     = (const int*)  d_in[3];
    const float* freqs    = (const float*)d_in[5+ro];
    const float* pad      = (const float*)d_in[6+ro];
    const float* w_span   = (const float*)d_in[8+ro];
    const float* w_norm1  = (const float*)d_in[9+ro];
    const float* wq       = (const float*)d_in[10+ro];
    const float* wk       = (const float*)d_in[11+ro];
    const float* wv       = (const float*)d_in[12+ro];
    const float* wo       = (const float*)d_in[13+ro];
    const float* w_norm2  = (const float*)d_in[14+ro];
    const float* w1       = (const float*)d_in[15+ro];
    const float* w3       = (const float*)d_in[16+ro];
    const float* w2       = (const float*)d_in[17+ro];
    const float* w_metric = (const float*)d_in[18+ro];
    float* out = (float*)d_out;

    float *px2, *ph, *pq, *pk, *pv, *po, *pf1, *psim;
    int *pflag, *ppf;
    cudaGetSymbolAddress((void**)&px2,  g_x2);
    cudaGetSymbolAddress((void**)&ph,   g_h);
    cudaGetSymbolAddress((void**)&pq,   g_q);
    cudaGetSymbolAddress((void**)&pk,   g_k);
    cudaGetSymbolAddress((void**)&pv,   g_v);
    cudaGetSymbolAddress((void**)&po,   g_o);
    cudaGetSymbolAddress((void**)&pf1,  g_f1);
    cudaGetSymbolAddress((void**)&psim, g_sim);
    cudaGetSymbolAddress((void**)&pflag,g_flag);
    cudaGetSymbolAddress((void**)&ppf,  g_pf);

    // 1) x2 = x + span-embed ; h = rmsnorm1(x2)
    rmsnorm_k<true><<<BS, 256>>>(x, span, w_span, w_norm1, px2, ph);
    // 2) q,k,v projections
    dim3 gD(Dc/128, BS/128);
    sgemm_db<0><<<gD, 256>>>(ph, wq, nullptr, pq, BS, Dc, Dc);
    sgemm_db<0><<<gD, 256>>>(ph, wk, nullptr, pk, BS, Dc, Dc);
    sgemm_db<0><<<gD, 256>>>(ph, wv, nullptr, pv, BS, Dc, Dc);
    // 3) rope on q,k
    rope_kernel<<<(Bc*Sc*Hh*32)/256, 256>>>(pq, pk, pos_ids, freqs);
    // 4) windowed attention
    attn_kernel<<<Bc*NWc*Hh, 256>>>(pq, pk, pv, po);
    // 5) x3 = x2 + o @ wo  (in place into g_x2)
    sgemm_db<1><<<gD, 256>>>(po, wo, px2, px2, BS, Dc, Dc);
    // 6) h = rmsnorm2(x3)
    rmsnorm_k<false><<<BS, 256>>>(px2, nullptr, nullptr, w_norm2, nullptr, ph);
    // 7) FFN: f1 = h@w1 ; f1 = silu(f1) * (h@w3)  [gate fused in epilogue]
    dim3 gF(FFc/128, BS/128);
    sgemm_db<0><<<gF, 256>>>(ph, w1, nullptr, pf1, BS, FFc, Dc);
    sgemm_db<2><<<gF, 256>>>(ph, w3, pf1, pf1, BS, FFc, Dc);
    // 8) x4 = x3 + gated @ w2  (in place)
    sgemm_db<1><<<gD, 256>>>(pf1, w2, px2, px2, BS, Dc, FFc);
    // 9) metric + cosine sim per pair
    pair_sim<<<Bc*PAIRS, 256>>>(px2, source, pad, w_metric, psim);
    // 10) exact top-k flags + prefix
    topk_kernel<<<Bc, 1024>>>(psim, pflag, ppf);
    // 11) merge + gather + emit
    emit_kernel<<<Bc*Sc, 256>>>(px2, source, pos_ids, span, pflag, ppf, out);
    (void)in_sizes; (void)out_size;
}